// round 16
// baseline (speedup 1.0000x reference)
#include <cuda_runtime.h>
#include <cuda_fp16.h>
#include <stdint.h>
#include <math.h>

#define EMBED 1024
#define HEADS 16
#define HDIM  64
#define SEQ   2048
#define BATCH 2
#define MTOT  (BATCH * SEQ)   // 4096

// ---------------- scratch (device globals; no allocation) ----------------
__device__ __half g_qh[BATCH * HEADS * SEQ * HDIM];   // fp16 [b,h,l,d], Q pre-scaled log2e/32
__device__ __half g_kh[BATCH * HEADS * SEQ * HDIM];
__device__ __half g_vh[BATCH * HEADS * SEQ * HDIM];

__device__ __half g_xh[MTOT * EMBED];                 // x fp16
__device__ __half g_w3h[3 * EMBED * EMBED];           // Wq|Wk|Wv fp16
__device__ __half g_woh[EMBED * EMBED];               // Wo fp16
__device__ __half g_ah[MTOT * EMBED];                 // attn out fp16

// =====================================================================
// PTX helpers
// =====================================================================
__device__ __forceinline__ uint32_t smem_u32(const void* p) {
    uint32_t a;
    asm("{ .reg .u64 t; cvta.to.shared.u64 t, %1; cvt.u32.u64 %0, t; }"
        : "=r"(a) : "l"(p));
    return a;
}
__device__ __forceinline__ void mma_f16(float* c, const uint32_t* a, const uint32_t* b) {
    asm volatile("mma.sync.aligned.m16n8k16.row.col.f32.f16.f16.f32 "
        "{%0,%1,%2,%3}, {%4,%5,%6,%7}, {%8,%9}, {%0,%1,%2,%3};"
        : "+f"(c[0]), "+f"(c[1]), "+f"(c[2]), "+f"(c[3])
        : "r"(a[0]), "r"(a[1]), "r"(a[2]), "r"(a[3]), "r"(b[0]), "r"(b[1]));
}
// fp16-accumulator HMMA
__device__ __forceinline__ void mma_f16h(uint32_t* c, const uint32_t* a, const uint32_t* b) {
    asm volatile("mma.sync.aligned.m16n8k16.row.col.f16.f16.f16.f16 "
        "{%0,%1}, {%2,%3,%4,%5}, {%6,%7}, {%0,%1};"
        : "+r"(c[0]), "+r"(c[1])
        : "r"(a[0]), "r"(a[1]), "r"(a[2]), "r"(a[3]), "r"(b[0]), "r"(b[1]));
}
__device__ __forceinline__ void ldsm4(uint32_t* r, uint32_t a) {
    asm volatile("ldmatrix.sync.aligned.m8n8.x4.shared.b16 {%0,%1,%2,%3}, [%4];"
        : "=r"(r[0]), "=r"(r[1]), "=r"(r[2]), "=r"(r[3]) : "r"(a));
}
__device__ __forceinline__ void ldsm4t(uint32_t* r, uint32_t a) {
    asm volatile("ldmatrix.sync.aligned.m8n8.x4.trans.shared.b16 {%0,%1,%2,%3}, [%4];"
        : "=r"(r[0]), "=r"(r[1]), "=r"(r[2]), "=r"(r[3]) : "r"(a));
}
#define CP16(dst, src) \
    asm volatile("cp.async.cg.shared.global [%0], [%1], 16;" \
                 :: "r"((uint32_t)(dst)), "l"(src) : "memory")
#define CPCOMMIT() asm volatile("cp.async.commit_group;" ::: "memory")
#define CPWAIT0()  asm volatile("cp.async.wait_group 0;" ::: "memory")

__device__ __forceinline__ uint32_t h2ex2(uint32_t x) {
    uint32_t r;
    asm("ex2.approx.f16x2 %0, %1;" : "=r"(r) : "r"(x));
    return r;
}

// =====================================================================
// fp32 -> fp16 converts
// =====================================================================
__global__ void cvt_f16_kernel(const float* __restrict__ src,
                               __half* __restrict__ dst, int n)
{
    int i = (blockIdx.x * blockDim.x + threadIdx.x) * 4;
    if (i >= n) return;
    float4 v = *(const float4*)(src + i);
    *(__half2*)(dst + i)     = __floats2half2_rn(v.x, v.y);
    *(__half2*)(dst + i + 2) = __floats2half2_rn(v.z, v.w);
}

__global__ void cvt4_f16_kernel(const float* __restrict__ s0, __half* __restrict__ d0,
                                const float* __restrict__ s1, __half* __restrict__ d1,
                                const float* __restrict__ s2, __half* __restrict__ d2,
                                const float* __restrict__ s3, __half* __restrict__ d3,
                                int n)
{
    const float* src = (blockIdx.y == 0) ? s0 : (blockIdx.y == 1) ? s1
                     : (blockIdx.y == 2) ? s2 : s3;
    __half* dst      = (blockIdx.y == 0) ? d0 : (blockIdx.y == 1) ? d1
                     : (blockIdx.y == 2) ? d2 : d3;
    int i = (blockIdx.x * blockDim.x + threadIdx.x) * 4;
    if (i >= n) return;
    float4 v = *(const float4*)(src + i);
    *(__half2*)(dst + i)     = __floats2half2_rn(v.x, v.y);
    *(__half2*)(dst + i + 2) = __floats2half2_rn(v.z, v.w);
}

// =====================================================================
// mma.sync GEMM NT, single fp16: C = A * B^T.
// BM=BN=128, BK=64 per stage, 256 thr (2x4 warps), 2-stage cp.async,
// ONE wait+barrier per 64-wide chunk (16 total). Rows padded to 144B.
// =====================================================================
#define GTS     (128 * 144)              // 18432 B per tensor-tile (128 rows x 144B)
#define GSTAGE  (2 * GTS)                // 36864 B per stage (A, B)
#define GSMEM   (2 * GSTAGE)             // 73728 B

#define NCHUNK (EMBED / 64)              // 16

__global__ __launch_bounds__(256, 2)
void gemm_mma_kernel(const __half* __restrict__ Ah,
                     const __half* __restrict__ Bh,
                     float* __restrict__ Cout,
                     const float* __restrict__ bias,
                     int mode)
{
    extern __shared__ char smem[];
    const uint32_t sb = smem_u32(smem);
    const int tid = threadIdx.x;
    const int lane = tid & 31, wid = tid >> 5;
    const int wm = wid & 1, wn = wid >> 1;    // 2 x 4 warp grid
    const int m0 = blockIdx.y * 128, n0 = blockIdx.x * 128;

    const int r0 = tid >> 1, cc = tid & 1;    // 128 rows x 2 half-rows

    const __half* gsrc[2] = {
        Ah + (size_t)m0 * EMBED, Bh + (size_t)n0 * EMBED };

    const uint32_t frag_loff = (uint32_t)((lane & 15) * 144) + (lane >> 4) * 16;

    float acc[4][4][4];
    #pragma unroll
    for (int mt = 0; mt < 4; mt++)
        #pragma unroll
        for (int nt = 0; nt < 4; nt++)
            #pragma unroll
            for (int i = 0; i < 4; i++)
                acc[mt][nt][i] = 0.0f;

    // preload chunk 0 into stage 0
    #pragma unroll
    for (int t = 0; t < 2; t++)
        #pragma unroll
        for (int i = 0; i < 4; i++)
            CP16(sb + t * GTS + r0 * 144 + cc * 64 + i * 16,
                 gsrc[t] + (size_t)r0 * EMBED + cc * 32 + i * 8);
    CPCOMMIT();

    for (int c = 0; c < NCHUNK; c++) {
        CPWAIT0();            // chunk c resident
        __syncthreads();      // all warps past compute of c-1; stage safe

        // prefetch chunk c+1 into the other stage (full iteration of slack)
        if (c + 1 < NCHUNK) {
            const int k0 = (c + 1) * 64;
            const uint32_t stb = sb + ((c + 1) & 1) * GSTAGE;
            #pragma unroll
            for (int t = 0; t < 2; t++)
                #pragma unroll
                for (int i = 0; i < 4; i++)
                    CP16(stb + t * GTS + r0 * 144 + cc * 64 + i * 16,
                         gsrc[t] + (size_t)r0 * EMBED + k0 + cc * 32 + i * 8);
        }
        CPCOMMIT();

        const uint32_t base = sb + (c & 1) * GSTAGE;
        #pragma unroll
        for (int kk = 0; kk < 4; kk++) {
            uint32_t ah[4][4];
            #pragma unroll
            for (int mt = 0; mt < 4; mt++) {
                uint32_t ro = (uint32_t)((wm * 64 + mt * 16) * 144) + kk * 32 + frag_loff;
                ldsm4(ah[mt], base + 0 * GTS + ro);
            }
            uint32_t bh[2][4];
            #pragma unroll
            for (int p = 0; p < 2; p++) {
                uint32_t ro = (uint32_t)((wn * 32 + p * 16) * 144) + kk * 32 + frag_loff;
                ldsm4(bh[p], base + 1 * GTS + ro);
            }
            #pragma unroll
            for (int mt = 0; mt < 4; mt++)
                #pragma unroll
                for (int nt = 0; nt < 4; nt++) {
                    const int p = nt >> 1, q = nt & 1;
                    uint32_t bfh[2] = { bh[p][q], bh[p][q + 2] };
                    mma_f16(acc[mt][nt], ah[mt], bfh);
                }
        }
        // no trailing sync; stage reuse gated by next iteration's barrier
    }

    // epilogue
    const int lq = lane >> 2, lr2 = (lane & 3) * 2;
    if (mode == 1) {
        #pragma unroll
        for (int mt = 0; mt < 4; mt++) {
            int m = m0 + wm * 64 + mt * 16 + lq;
            #pragma unroll
            for (int nt = 0; nt < 4; nt++) {
                int n = n0 + wn * 32 + nt * 8 + lr2;
                float2 b2 = *(const float2*)(bias + n);
                float2 vlo = make_float2(acc[mt][nt][0] + b2.x, acc[mt][nt][1] + b2.y);
                float2 vhi = make_float2(acc[mt][nt][2] + b2.x, acc[mt][nt][3] + b2.y);
                *(float2*)(Cout + (size_t)m * EMBED + n) = vlo;
                *(float2*)(Cout + (size_t)(m + 8) * EMBED + n) = vhi;
            }
        }
    } else {
        const int sel = n0 >> 10;
        __half* dst = (sel == 0) ? g_qh : (sel == 1) ? g_kh : g_vh;
        // Q pre-scale: (1/sqrt(1024)) * log2(e) -> attention in exp2 domain
        const float sc = (sel == 0) ? 0.0450842204f : 1.0f;
        #pragma unroll
        for (int mt = 0; mt < 4; mt++) {
            int m = m0 + wm * 64 + mt * 16 + lq;
            int bb = m >> 11;
            int l = m & 2047;
            #pragma unroll
            for (int nt = 0; nt < 4; nt++) {
                int ng = n0 + wn * 32 + nt * 8 + lr2;
                int rem = ng & 1023;
                int h = rem >> 6, d = rem & 63;
                __half2 vlo = __floats2half2_rn(acc[mt][nt][0] * sc, acc[mt][nt][1] * sc);
                __half2 vhi = __floats2half2_rn(acc[mt][nt][2] * sc, acc[mt][nt][3] * sc);
                size_t hb = ((size_t)(bb * HEADS + h) * SEQ) * HDIM + d;
                *(__half2*)(dst + hb + (size_t)l * HDIM) = vlo;
                *(__half2*)(dst + hb + (size_t)(l + 8) * HDIM) = vhi;
            }
        }
    }
}

// =====================================================================
// Flash attention: stage = 128 keys (two 64-key sub-tiles share one
// wait+barrier; S regs reused). 8 warps x 16 q-rows; fp16-accum QK,
// in-place ex2.f16x2, ones-MMA row sums, fp32-accum PV. 2-stage
// cp.async, 2 CTAs/SM.
// =====================================================================
#define ASM_Q    0
#define AQB      (128 * 144)             // 18432
#define ASM_K    AQB
#define AKSTAGE  (128 * 144)             // 18432 (128 keys x 144B)
#define ASM_V    (ASM_K + 2 * AKSTAGE)
#define ASMEM    (ASM_V + 2 * AKSTAGE)   // 92160

#define NKT2 (SEQ / 128)                 // 16

__global__ __launch_bounds__(256, 2)
void attn_mma_kernel()
{
    extern __shared__ char smem[];
    const uint32_t sb = smem_u32(smem);
    const int tid = threadIdx.x, lane = tid & 31, w = tid >> 5;
    const int qt = blockIdx.x, h = blockIdx.y, b = blockIdx.z;
    const size_t hb = (size_t)(b * HEADS + h) * SEQ * HDIM;
    const __half* gq = g_qh + hb + (size_t)qt * 128 * HDIM;
    const __half* gk = g_kh + hb;
    const __half* gv = g_vh + hb;

    const int r = tid >> 1, cc = tid & 1;    // 128 key-rows x 2 half-rows

    // preload K/V tile 0 (128 keys) into stage 0
    #pragma unroll
    for (int i = 0; i < 4; i++) {
        CP16(sb + ASM_K + r * 144 + cc * 64 + i * 16, gk + (size_t)r * HDIM + cc * 32 + i * 8);
        CP16(sb + ASM_V + r * 144 + cc * 64 + i * 16, gv + (size_t)r * HDIM + cc * 32 + i * 8);
    }
    CPCOMMIT();

    // Q copy (128 rows x 128B)
    {
        int qr = tid >> 1, ub = (tid & 1) * 4;
        #pragma unroll
        for (int i = 0; i < 4; i++) {
            uint4 v = *(const uint4*)(gq + qr * HDIM + (ub + i) * 8);
            *(uint4*)(smem + ASM_Q + qr * 144 + (ub + i) * 16) = v;
        }
    }
    __syncthreads();

    uint32_t qf[4][4];
    {
        uint32_t qaddr = sb + ASM_Q + (uint32_t)((w * 16 + (lane & 15)) * 144) + (lane >> 4) * 16;
        #pragma unroll
        for (int kk = 0; kk < 4; kk++) ldsm4(qf[kk], qaddr + kk * 32);
    }

    float oacc[8][4];
    #pragma unroll
    for (int dt = 0; dt < 8; dt++)
        #pragma unroll
        for (int i = 0; i < 4; i++) oacc[dt][i] = 0.0f;
    float lacc[4] = {0.0f, 0.0f, 0.0f, 0.0f};
    const uint32_t ones_frag[2] = { 0x3C003C00u, 0x3C003C00u };  // half2(1,1)

    const uint32_t kfb = sb + ASM_K + (uint32_t)((lane & 15) * 144) + (lane >> 4) * 16;
    const uint32_t vfb = sb + ASM_V + (uint32_t)((lane & 15) * 144) + (lane >> 4) * 16;

    for (int kt = 0; kt < NKT2; kt++) {
        CPWAIT0();            // tile kt resident
        __syncthreads();      // all warps past compute of kt-1

        // prefetch tile kt+1 into the other stage
        if (kt + 1 < NKT2) {
            const __half* gk2 = gk + (size_t)(kt + 1) * 128 * HDIM;
            const __half* gv2 = gv + (size_t)(kt + 1) * 128 * HDIM;
            const uint32_t st2 = ((kt + 1) & 1) * AKSTAGE;
            #pragma unroll
            for (int i = 0; i < 4; i++) {
                CP16(sb + ASM_K + st2 + r * 144 + cc * 64 + i * 16,
                     gk2 + (size_t)r * HDIM + cc * 32 + i * 8);
                CP16(sb + ASM_V + st2 + r * 144 + cc * 64 + i * 16,
                     gv2 + (size_t)r * HDIM + cc * 32 + i * 8);
            }
        }
        CPCOMMIT();

        const uint32_t st = (kt & 1) * AKSTAGE;

        // two 64-key sub-tiles, S regs reused
        #pragma unroll
        for (int sub = 0; sub < 2; sub++) {
            const uint32_t so = st + (uint32_t)(sub * 64 * 144);

            // S = Q K^T with fp16 accumulators
            uint32_t sh[8][2];
            #pragma unroll
            for (int nt = 0; nt < 8; nt++) { sh[nt][0] = 0u; sh[nt][1] = 0u; }
            #pragma unroll
            for (int kk = 0; kk < 4; kk++) {
                #pragma unroll
                for (int p = 0; p < 4; p++) {
                    uint32_t kr[4];
                    ldsm4(kr, kfb + so + (uint32_t)(p * 16 * 144) + kk * 32);
                    uint32_t b0[2] = { kr[0], kr[2] };
                    uint32_t b1[2] = { kr[1], kr[3] };
                    mma_f16h(sh[2 * p],     qf[kk], b0);
                    mma_f16h(sh[2 * p + 1], qf[kk], b1);
                }
            }

            // p = exp2(S) in place
            #pragma unroll
            for (int nt = 0; nt < 8; nt++) {
                sh[nt][0] = h2ex2(sh[nt][0]);
                sh[nt][1] = h2ex2(sh[nt][1]);
            }

            // row sums via ones-MMA
            #pragma unroll
            for (int jt = 0; jt < 4; jt++) {
                uint32_t af[4] = { sh[2 * jt][0], sh[2 * jt][1],
                                   sh[2 * jt + 1][0], sh[2 * jt + 1][1] };
                mma_f16(lacc, af, ones_frag);
            }

            // O += P V
            #pragma unroll
            for (int dp = 0; dp < 4; dp++) {
                #pragma unroll
                for (int jt = 0; jt < 4; jt++) {
                    uint32_t af[4] = { sh[2 * jt][0], sh[2 * jt][1],
                                       sh[2 * jt + 1][0], sh[2 * jt + 1][1] };
                    uint32_t vr[4];
                    ldsm4t(vr, vfb + so + (uint32_t)(jt * 16 * 144) + dp * 32);
                    mma_f16(oacc[2 * dp],     af, vr);
                    mma_f16(oacc[2 * dp + 1], af, vr + 2);
                }
            }
        }
        // no trailing sync (stage reuse gated by next barrier)
    }

    // epilogue: every lane holds full row sums
    const float inv_lo = 1.0f / lacc[0], inv_hi = 1.0f / lacc[2];
    const int row_lo = b * SEQ + qt * 128 + w * 16 + (lane >> 2);
    const int e0 = h * HDIM + (lane & 3) * 2;
    #pragma unroll
    for (int dt = 0; dt < 8; dt++) {
        *(__half2*)(g_ah + (size_t)row_lo * EMBED + e0 + dt * 8) =
            __floats2half2_rn(oacc[dt][0] * inv_lo, oacc[dt][1] * inv_lo);
        *(__half2*)(g_ah + (size_t)(row_lo + 8) * EMBED + e0 + dt * 8) =
            __floats2half2_rn(oacc[dt][2] * inv_hi, oacc[dt][3] * inv_hi);
    }
}

// =====================================================================
// Launch
// =====================================================================
extern "C" void kernel_launch(void* const* d_in, const int* in_sizes, int n_in,
                              void* d_out, int out_size)
{
    const float* x  = (const float*)d_in[0];
    const float* Wq = (const float*)d_in[1];
    const float* Wk = (const float*)d_in[2];
    const float* Wv = (const float*)d_in[3];
    const float* Wo = (const float*)d_in[4];
    const float* bo = (const float*)d_in[5];
    float* out = (float*)d_out;

    cudaFuncSetAttribute(gemm_mma_kernel,
                         cudaFuncAttributeMaxDynamicSharedMemorySize, GSMEM);
    cudaFuncSetAttribute(attn_mma_kernel,
                         cudaFuncAttributeMaxDynamicSharedMemorySize, ASMEM);

    __half *xh, *w3h, *woh, *ah;
    cudaGetSymbolAddress((void**)&xh,  g_xh);
    cudaGetSymbolAddress((void**)&w3h, g_w3h);
    cudaGetSymbolAddress((void**)&woh, g_woh);
    cudaGetSymbolAddress((void**)&ah,  g_ah);

    const int NX = MTOT * EMBED;       // 4M
    const int NW = EMBED * EMBED;      // 1M

    cvt_f16_kernel<<<NX / 1024, 256>>>(x, xh, NX);
    dim3 gw(NW / 1024, 4);
    cvt4_f16_kernel<<<gw, 256>>>(Wq, w3h, Wk, w3h + NW, Wv, w3h + 2 * NW, Wo, woh, NW);

    dim3 gqkv(3 * EMBED / 128, MTOT / 128);
    gemm_mma_kernel<<<gqkv, 256, GSMEM>>>(xh, w3h, nullptr, nullptr, 0);

    dim3 gattn(SEQ / 128, HEADS, BATCH);
    attn_mma_kernel<<<gattn, 256, ASMEM>>>();

    dim3 gout(EMBED / 128, MTOT / 128);
    gemm_mma_kernel<<<gout, 256, GSMEM>>>(ah, woh, out, bo, 1);
}

// round 17
// speedup vs baseline: 1.1789x; 1.1789x over previous
#include <cuda_runtime.h>
#include <cuda_fp16.h>
#include <stdint.h>
#include <math.h>

#define EMBED 1024
#define HEADS 16
#define HDIM  64
#define SEQ   2048
#define BATCH 2
#define MTOT  (BATCH * SEQ)   // 4096

// ---------------- scratch (device globals; no allocation) ----------------
__device__ __half g_qh[BATCH * HEADS * SEQ * HDIM];   // fp16 [b,h,l,d], Q pre-scaled log2e/32
__device__ __half g_kh[BATCH * HEADS * SEQ * HDIM];
__device__ __half g_vh[BATCH * HEADS * SEQ * HDIM];

__device__ __half g_xh[MTOT * EMBED];                 // x fp16
__device__ __half g_w3h[3 * EMBED * EMBED];           // Wq|Wk|Wv fp16
__device__ __half g_woh[EMBED * EMBED];               // Wo fp16
__device__ __half g_ah[MTOT * EMBED];                 // attn out fp16

// =====================================================================
// PTX helpers
// =====================================================================
__device__ __forceinline__ uint32_t smem_u32(const void* p) {
    uint32_t a;
    asm("{ .reg .u64 t; cvta.to.shared.u64 t, %1; cvt.u32.u64 %0, t; }"
        : "=r"(a) : "l"(p));
    return a;
}
__device__ __forceinline__ void mma_f16(float* c, const uint32_t* a, const uint32_t* b) {
    asm volatile("mma.sync.aligned.m16n8k16.row.col.f32.f16.f16.f32 "
        "{%0,%1,%2,%3}, {%4,%5,%6,%7}, {%8,%9}, {%0,%1,%2,%3};"
        : "+f"(c[0]), "+f"(c[1]), "+f"(c[2]), "+f"(c[3])
        : "r"(a[0]), "r"(a[1]), "r"(a[2]), "r"(a[3]), "r"(b[0]), "r"(b[1]));
}
// fp16-accumulator HMMA
__device__ __forceinline__ void mma_f16h(uint32_t* c, const uint32_t* a, const uint32_t* b) {
    asm volatile("mma.sync.aligned.m16n8k16.row.col.f16.f16.f16.f16 "
        "{%0,%1}, {%2,%3,%4,%5}, {%6,%7}, {%0,%1};"
        : "+r"(c[0]), "+r"(c[1])
        : "r"(a[0]), "r"(a[1]), "r"(a[2]), "r"(a[3]), "r"(b[0]), "r"(b[1]));
}
__device__ __forceinline__ void ldsm4(uint32_t* r, uint32_t a) {
    asm volatile("ldmatrix.sync.aligned.m8n8.x4.shared.b16 {%0,%1,%2,%3}, [%4];"
        : "=r"(r[0]), "=r"(r[1]), "=r"(r[2]), "=r"(r[3]) : "r"(a));
}
__device__ __forceinline__ void ldsm4t(uint32_t* r, uint32_t a) {
    asm volatile("ldmatrix.sync.aligned.m8n8.x4.trans.shared.b16 {%0,%1,%2,%3}, [%4];"
        : "=r"(r[0]), "=r"(r[1]), "=r"(r[2]), "=r"(r[3]) : "r"(a));
}
#define CP16(dst, src) \
    asm volatile("cp.async.cg.shared.global [%0], [%1], 16;" \
                 :: "r"((uint32_t)(dst)), "l"(src) : "memory")
#define CPCOMMIT() asm volatile("cp.async.commit_group;" ::: "memory")
#define CPWAIT1()  asm volatile("cp.async.wait_group 1;" ::: "memory")

__device__ __forceinline__ uint32_t h2ex2(uint32_t x) {
    uint32_t r;
    asm("ex2.approx.f16x2 %0, %1;" : "=r"(r) : "r"(x));
    return r;
}

// =====================================================================
// fp32 -> fp16 converts
// =====================================================================
__global__ void cvt_f16_kernel(const float* __restrict__ src,
                               __half* __restrict__ dst, int n)
{
    int i = (blockIdx.x * blockDim.x + threadIdx.x) * 4;
    if (i >= n) return;
    float4 v = *(const float4*)(src + i);
    *(__half2*)(dst + i)     = __floats2half2_rn(v.x, v.y);
    *(__half2*)(dst + i + 2) = __floats2half2_rn(v.z, v.w);
}

__global__ void cvt4_f16_kernel(const float* __restrict__ s0, __half* __restrict__ d0,
                                const float* __restrict__ s1, __half* __restrict__ d1,
                                const float* __restrict__ s2, __half* __restrict__ d2,
                                const float* __restrict__ s3, __half* __restrict__ d3,
                                int n)
{
    const float* src = (blockIdx.y == 0) ? s0 : (blockIdx.y == 1) ? s1
                     : (blockIdx.y == 2) ? s2 : s3;
    __half* dst      = (blockIdx.y == 0) ? d0 : (blockIdx.y == 1) ? d1
                     : (blockIdx.y == 2) ? d2 : d3;
    int i = (blockIdx.x * blockDim.x + threadIdx.x) * 4;
    if (i >= n) return;
    float4 v = *(const float4*)(src + i);
    *(__half2*)(dst + i)     = __floats2half2_rn(v.x, v.y);
    *(__half2*)(dst + i + 2) = __floats2half2_rn(v.z, v.w);
}

// =====================================================================
// mma.sync GEMM NT, single fp16 (round-12 proven config, best measured):
// BM=BN=128, BK=32, 256 thr (2x4 warps), cp.async 2-stage, 2 CTAs/SM.
// =====================================================================
#define GSTRIDE 40                       // fp16 elems per smem row (80B)
#define GTS     (128 * GSTRIDE * 2)      // 10240 B per tensor-tile
#define GSTAGE  (2 * GTS)                // 20480 B per stage (A, B)
#define GSMEM   (2 * GSTAGE)             // 40960 B

__global__ __launch_bounds__(256, 2)
void gemm_mma_kernel(const __half* __restrict__ Ah,
                     const __half* __restrict__ Bh,
                     float* __restrict__ Cout,
                     const float* __restrict__ bias,
                     int mode)
{
    extern __shared__ char smem[];
    const uint32_t sb = smem_u32(smem);
    const int tid = threadIdx.x;
    const int lane = tid & 31, wid = tid >> 5;
    const int wm = wid & 1, wn = wid >> 1;    // 2 x 4 warp grid
    const int m0 = blockIdx.y * 128, n0 = blockIdx.x * 128;

    const int r0 = tid >> 2, cc = tid & 3;

    const __half* gsrc[2] = {
        Ah + (size_t)m0 * EMBED, Bh + (size_t)n0 * EMBED };

    const uint32_t frag_loff = (uint32_t)((lane & 15) * (GSTRIDE * 2)) + (lane >> 4) * 16;

    float acc[4][4][4];
    #pragma unroll
    for (int mt = 0; mt < 4; mt++)
        #pragma unroll
        for (int nt = 0; nt < 4; nt++)
            #pragma unroll
            for (int i = 0; i < 4; i++)
                acc[mt][nt][i] = 0.0f;

    #pragma unroll
    for (int t = 0; t < 2; t++) {
        #pragma unroll
        for (int u = 0; u < 2; u++) {
            int row = r0 + u * 64;
            CP16(sb + t * GTS + row * (GSTRIDE * 2) + cc * 16,
                 gsrc[t] + (size_t)row * EMBED + cc * 8);
        }
    }
    CPCOMMIT();

    for (int c = 0; c < EMBED / 32; c++) {
        if (c + 1 < EMBED / 32) {
            const int k0 = (c + 1) * 32;
            const uint32_t stb = sb + ((c + 1) & 1) * GSTAGE;
            #pragma unroll
            for (int t = 0; t < 2; t++) {
                #pragma unroll
                for (int u = 0; u < 2; u++) {
                    int row = r0 + u * 64;
                    CP16(stb + t * GTS + row * (GSTRIDE * 2) + cc * 16,
                         gsrc[t] + (size_t)row * EMBED + k0 + cc * 8);
                }
            }
        }
        CPCOMMIT();
        CPWAIT1();
        __syncthreads();

        const uint32_t base = sb + (c & 1) * GSTAGE;
        #pragma unroll
        for (int kk = 0; kk < 2; kk++) {
            uint32_t ah[4][4];
            #pragma unroll
            for (int mt = 0; mt < 4; mt++) {
                uint32_t ro = (uint32_t)((wm * 64 + mt * 16) * (GSTRIDE * 2)) + kk * 32 + frag_loff;
                ldsm4(ah[mt], base + 0 * GTS + ro);
            }
            uint32_t bh[2][4];
            #pragma unroll
            for (int p = 0; p < 2; p++) {
                uint32_t ro = (uint32_t)((wn * 32 + p * 16) * (GSTRIDE * 2)) + kk * 32 + frag_loff;
                ldsm4(bh[p], base + 1 * GTS + ro);
            }
            #pragma unroll
            for (int mt = 0; mt < 4; mt++)
                #pragma unroll
                for (int nt = 0; nt < 4; nt++) {
                    const int p = nt >> 1, q = nt & 1;
                    uint32_t bfh[2] = { bh[p][q], bh[p][q + 2] };
                    mma_f16(acc[mt][nt], ah[mt], bfh);
                }
        }
        __syncthreads();
    }

    // epilogue
    const int lq = lane >> 2, lr2 = (lane & 3) * 2;
    if (mode == 1) {
        #pragma unroll
        for (int mt = 0; mt < 4; mt++) {
            int m = m0 + wm * 64 + mt * 16 + lq;
            #pragma unroll
            for (int nt = 0; nt < 4; nt++) {
                int n = n0 + wn * 32 + nt * 8 + lr2;
                float2 b2 = *(const float2*)(bias + n);
                float2 vlo = make_float2(acc[mt][nt][0] + b2.x, acc[mt][nt][1] + b2.y);
                float2 vhi = make_float2(acc[mt][nt][2] + b2.x, acc[mt][nt][3] + b2.y);
                *(float2*)(Cout + (size_t)m * EMBED + n) = vlo;
                *(float2*)(Cout + (size_t)(m + 8) * EMBED + n) = vhi;
            }
        }
    } else {
        const int sel = n0 >> 10;
        __half* dst = (sel == 0) ? g_qh : (sel == 1) ? g_kh : g_vh;
        // Q pre-scale: (1/sqrt(1024)) * log2(e) -> attention in exp2 domain
        const float sc = (sel == 0) ? 0.0450842204f : 1.0f;
        #pragma unroll
        for (int mt = 0; mt < 4; mt++) {
            int m = m0 + wm * 64 + mt * 16 + lq;
            int bb = m >> 11;
            int l = m & 2047;
            #pragma unroll
            for (int nt = 0; nt < 4; nt++) {
                int ng = n0 + wn * 32 + nt * 8 + lr2;
                int rem = ng & 1023;
                int h = rem >> 6, d = rem & 63;
                __half2 vlo = __floats2half2_rn(acc[mt][nt][0] * sc, acc[mt][nt][1] * sc);
                __half2 vhi = __floats2half2_rn(acc[mt][nt][2] * sc, acc[mt][nt][3] * sc);
                size_t hb = ((size_t)(bb * HEADS + h) * SEQ) * HDIM + d;
                *(__half2*)(dst + hb + (size_t)l * HDIM) = vlo;
                *(__half2*)(dst + hb + (size_t)(l + 8) * HDIM) = vhi;
            }
        }
    }
}

// =====================================================================
// Flash attention (round-15 proven config, best measured): 8 warps x
// 16 q-rows, fp16-accum QK, in-place ex2.f16x2, ones-MMA row sums,
// fp32-accum PV, 3-stage cp.async with ONE barrier per iteration.
// 2 CTAs/SM.
// =====================================================================
#define ASM_Q   0
#define AQB     (128 * 144)              // 18432
#define ASM_K   AQB
#define AKSTAGE (64 * 144)               // 9216
#define ASM_V   (ASM_K + 3 * AKSTAGE)
#define ASMEM   (ASM_V + 3 * AKSTAGE)    // 73728

#define NKT (SEQ / 64)                   // 32

__global__ __launch_bounds__(256, 2)
void attn_mma_kernel()
{
    extern __shared__ char smem[];
    const uint32_t sb = smem_u32(smem);
    const int tid = threadIdx.x, lane = tid & 31, w = tid >> 5;
    const int qt = blockIdx.x, h = blockIdx.y, b = blockIdx.z;
    const size_t hb = (size_t)(b * HEADS + h) * SEQ * HDIM;
    const __half* gq = g_qh + hb + (size_t)qt * 128 * HDIM;
    const __half* gk = g_kh + hb;
    const __half* gv = g_vh + hb;

    const int r = tid >> 2, cc = tid & 3;

    // preload K/V tiles 0, 1 into stages 0, 1 (two committed groups)
    #pragma unroll
    for (int pt = 0; pt < 2; pt++) {
        const __half* gk0 = gk + (size_t)pt * 64 * HDIM;
        const __half* gv0 = gv + (size_t)pt * 64 * HDIM;
        const uint32_t st = pt * AKSTAGE;
        CP16(sb + ASM_K + st + r * 144 + cc * 16,       gk0 + r * HDIM + cc * 8);
        CP16(sb + ASM_K + st + r * 144 + (cc + 4) * 16, gk0 + r * HDIM + cc * 8 + 32);
        CP16(sb + ASM_V + st + r * 144 + cc * 16,       gv0 + r * HDIM + cc * 8);
        CP16(sb + ASM_V + st + r * 144 + (cc + 4) * 16, gv0 + r * HDIM + cc * 8 + 32);
        CPCOMMIT();
    }

    // Q copy
    {
        int qr = tid >> 1, ub = (tid & 1) * 4;
        #pragma unroll
        for (int i = 0; i < 4; i++) {
            uint4 v = *(const uint4*)(gq + qr * HDIM + (ub + i) * 8);
            *(uint4*)(smem + ASM_Q + qr * 144 + (ub + i) * 16) = v;
        }
    }
    __syncthreads();

    uint32_t qf[4][4];
    {
        uint32_t qaddr = sb + ASM_Q + (uint32_t)((w * 16 + (lane & 15)) * 144) + (lane >> 4) * 16;
        #pragma unroll
        for (int kk = 0; kk < 4; kk++) ldsm4(qf[kk], qaddr + kk * 32);
    }

    float oacc[8][4];
    #pragma unroll
    for (int dt = 0; dt < 8; dt++)
        #pragma unroll
        for (int i = 0; i < 4; i++) oacc[dt][i] = 0.0f;
    float lacc[4] = {0.0f, 0.0f, 0.0f, 0.0f};
    const uint32_t ones_frag[2] = { 0x3C003C00u, 0x3C003C00u };  // half2(1,1)

    const uint32_t kfb = sb + ASM_K + (uint32_t)((lane & 15) * 144) + (lane >> 4) * 16;
    const uint32_t vfb = sb + ASM_V + (uint32_t)((lane & 15) * 144) + (lane >> 4) * 16;

    for (int kt = 0; kt < NKT; kt++) {
        CPWAIT1();            // K/V group kt complete
        __syncthreads();      // publish stage kt; nobody still reads kt-1

        // prefetch tile kt+2 into stage (kt+2)%3 (not live)
        if (kt + 2 < NKT) {
            const __half* gk2 = gk + (size_t)(kt + 2) * 64 * HDIM;
            const __half* gv2 = gv + (size_t)(kt + 2) * 64 * HDIM;
            const uint32_t st2 = ((kt + 2) % 3) * AKSTAGE;
            CP16(sb + ASM_K + st2 + r * 144 + cc * 16,       gk2 + r * HDIM + cc * 8);
            CP16(sb + ASM_K + st2 + r * 144 + (cc + 4) * 16, gk2 + r * HDIM + cc * 8 + 32);
            CP16(sb + ASM_V + st2 + r * 144 + cc * 16,       gv2 + r * HDIM + cc * 8);
            CP16(sb + ASM_V + st2 + r * 144 + (cc + 4) * 16, gv2 + r * HDIM + cc * 8 + 32);
        }
        CPCOMMIT();

        const uint32_t st = (kt % 3) * AKSTAGE;

        // S = Q K^T with fp16 accumulators
        uint32_t sh[8][2];
        #pragma unroll
        for (int nt = 0; nt < 8; nt++) { sh[nt][0] = 0u; sh[nt][1] = 0u; }
        #pragma unroll
        for (int kk = 0; kk < 4; kk++) {
            #pragma unroll
            for (int p = 0; p < 4; p++) {
                uint32_t kr[4];
                ldsm4(kr, kfb + st + (uint32_t)(p * 16 * 144) + kk * 32);
                uint32_t b0[2] = { kr[0], kr[2] };
                uint32_t b1[2] = { kr[1], kr[3] };
                mma_f16h(sh[2 * p],     qf[kk], b0);
                mma_f16h(sh[2 * p + 1], qf[kk], b1);
            }
        }

        // p = exp2(S) in place
        #pragma unroll
        for (int nt = 0; nt < 8; nt++) {
            sh[nt][0] = h2ex2(sh[nt][0]);
            sh[nt][1] = h2ex2(sh[nt][1]);
        }

        // row sums via ones-MMA
        #pragma unroll
        for (int jt = 0; jt < 4; jt++) {
            uint32_t af[4] = { sh[2 * jt][0], sh[2 * jt][1],
                               sh[2 * jt + 1][0], sh[2 * jt + 1][1] };
            mma_f16(lacc, af, ones_frag);
        }

        // O += P V
        #pragma unroll
        for (int dp = 0; dp < 4; dp++) {
            #pragma unroll
            for (int jt = 0; jt < 4; jt++) {
                uint32_t af[4] = { sh[2 * jt][0], sh[2 * jt][1],
                                   sh[2 * jt + 1][0], sh[2 * jt + 1][1] };
                uint32_t vr[4];
                ldsm4t(vr, vfb + st + (uint32_t)(jt * 16 * 144) + dp * 32);
                mma_f16(oacc[2 * dp],     af, vr);
                mma_f16(oacc[2 * dp + 1], af, vr + 2);
            }
        }
        // no trailing sync (3-stage)
    }

    // epilogue: every lane holds full row sums
    const float inv_lo = 1.0f / lacc[0], inv_hi = 1.0f / lacc[2];
    const int row_lo = b * SEQ + qt * 128 + w * 16 + (lane >> 2);
    const int e0 = h * HDIM + (lane & 3) * 2;
    #pragma unroll
    for (int dt = 0; dt < 8; dt++) {
        *(__half2*)(g_ah + (size_t)row_lo * EMBED + e0 + dt * 8) =
            __floats2half2_rn(oacc[dt][0] * inv_lo, oacc[dt][1] * inv_lo);
        *(__half2*)(g_ah + (size_t)(row_lo + 8) * EMBED + e0 + dt * 8) =
            __floats2half2_rn(oacc[dt][2] * inv_hi, oacc[dt][3] * inv_hi);
    }
}

// =====================================================================
// Launch
// =====================================================================
extern "C" void kernel_launch(void* const* d_in, const int* in_sizes, int n_in,
                              void* d_out, int out_size)
{
    const float* x  = (const float*)d_in[0];
    const float* Wq = (const float*)d_in[1];
    const float* Wk = (const float*)d_in[2];
    const float* Wv = (const float*)d_in[3];
    const float* Wo = (const float*)d_in[4];
    const float* bo = (const float*)d_in[5];
    float* out = (float*)d_out;

    cudaFuncSetAttribute(gemm_mma_kernel,
                         cudaFuncAttributeMaxDynamicSharedMemorySize, GSMEM);
    cudaFuncSetAttribute(attn_mma_kernel,
                         cudaFuncAttributeMaxDynamicSharedMemorySize, ASMEM);

    __half *xh, *w3h, *woh, *ah;
    cudaGetSymbolAddress((void**)&xh,  g_xh);
    cudaGetSymbolAddress((void**)&w3h, g_w3h);
    cudaGetSymbolAddress((void**)&woh, g_woh);
    cudaGetSymbolAddress((void**)&ah,  g_ah);

    const int NX = MTOT * EMBED;       // 4M
    const int NW = EMBED * EMBED;      // 1M

    cvt_f16_kernel<<<NX / 1024, 256>>>(x, xh, NX);
    dim3 gw(NW / 1024, 4);
    cvt4_f16_kernel<<<gw, 256>>>(Wq, w3h, Wk, w3h + NW, Wv, w3h + 2 * NW, Wo, woh, NW);

    dim3 gqkv(3 * EMBED / 128, MTOT / 128);
    gemm_mma_kernel<<<gqkv, 256, GSMEM>>>(xh, w3h, nullptr, nullptr, 0);

    dim3 gattn(SEQ / 128, HEADS, BATCH);
    attn_mma_kernel<<<gattn, 256, ASMEM>>>();

    dim3 gout(EMBED / 128, MTOT / 128);
    gemm_mma_kernel<<<gout, 256, GSMEM>>>(ah, woh, out, bo, 1);
}